// round 15
// baseline (speedup 1.0000x reference)
#include <cuda_runtime.h>
#include <cuda_fp16.h>
#include <cstdint>

typedef unsigned long long u64;
typedef unsigned int u32;

// ---------------------------------------------------------------------------
// Scratch (no allocations allowed). Activation buffers hold either raw fp32
// rows or split-fp16 rows (u32[32]: 16 hi pairs + 16 lo pairs) — same bytes.
// ---------------------------------------------------------------------------
#define MAXN 450000
__device__ float g_bufA[(size_t)MAXN * 32];
__device__ float g_bufB[(size_t)MAXN * 32];
__device__ float g_bufC[(size_t)MAXN * 32];
__device__ float g_bufD[(size_t)MAXN * 32];
__device__ float g_stats[7 * 64];   // per layer: sum[32], sumsq[32]
__device__ u32 g_Bw[5 * 27 * 512 + 8 * 512];   // single-fp16 fragment weights
__device__ u32 g_Bs1[1792];

// ---------------------------------------------------------------------------
// helpers
// ---------------------------------------------------------------------------
__device__ __forceinline__ u32 packh(float x, float y) {
    __half2 h = __floats2half2_rn(x, y);
    return *(u32 *)&h;
}
__device__ __forceinline__ float2 unph(u32 u) {
    __half2 h = *(__half2 *)&u;
    return __half22float2(h);
}
__device__ __forceinline__ void cvtp(float x, float y, u32 &h, u32 &l) {
    h = packh(x, y);
    float2 r = unph(h);
    l = packh(x - r.x, y - r.y);
}
__device__ __forceinline__ void mma16816(float *d, const u32 *a, u32 b0, u32 b1) {
    asm volatile(
        "mma.sync.aligned.m16n8k16.row.col.f32.f16.f16.f32 "
        "{%0,%1,%2,%3}, {%4,%5,%6,%7}, {%8,%9}, {%0,%1,%2,%3};"
        : "+f"(d[0]), "+f"(d[1]), "+f"(d[2]), "+f"(d[3])
        : "r"(a[0]), "r"(a[1]), "r"(a[2]), "r"(a[3]), "r"(b0), "r"(b1));
}
// 8 MMAs: 2 passes (ah, al) x 4 nc against single-fp16 weights
__device__ __forceinline__ void mma_pass2(float *acc, const u32 *ah, const u32 *al,
                                          uint4 H0, uint4 H1) {
    mma16816(acc + 0,  ah, H0.x, H0.y);
    mma16816(acc + 0,  al, H0.x, H0.y);
    mma16816(acc + 4,  ah, H0.z, H0.w);
    mma16816(acc + 4,  al, H0.z, H0.w);
    mma16816(acc + 8,  ah, H1.x, H1.y);
    mma16816(acc + 8,  al, H1.x, H1.y);
    mma16816(acc + 12, ah, H1.z, H1.w);
    mma16816(acc + 12, al, H1.z, H1.w);
}
// BN scale/shift into smem (first 32 threads)
__device__ __forceinline__ void compute_ss(float *ssm, const float *stats,
                                           const float *gamma, const float *beta,
                                           float invN, int c) {
    float mu  = stats[c] * invN;
    float var = stats[32 + c] * invN - mu * mu;
    float sc = rsqrtf(var + 1e-5f) * gamma[c];
    ssm[c] = sc;
    ssm[32 + c] = beta[c] - mu * sc;
}

// ---------------------------------------------------------------------------
// Combined weight prep + stats zero (1 launch); fp16 single-precision weights.
// ---------------------------------------------------------------------------
__device__ void prep_w_body(const float *__restrict__ W, u32 *__restrict__ out,
                            int K, int t)
{
    if (t >= K * 512) return;
    int tap  = t >> 9;
    int r    = t & 511;
    int kc   = r >> 8;
    int c2   = (r >> 7) & 1;
    int lane = (r >> 2) & 31;
    int e    = r & 3;
    int nc   = c2 * 2 + (e >> 1);
    int h    = e & 1;
    int mm   = lane & 3;
    int n    = nc * 8 + (lane >> 2);
    int k0   = 8 * mm + 4 * kc + 2 * h;
    float w0 = W[((size_t)tap * 32 + k0) * 32 + n];
    float w1 = W[((size_t)tap * 32 + k0 + 1) * 32 + n];
    out[t] = packh(w0, w1);
}

__global__ void prep_all(const float *W1, const float *W2, const float *W3,
                         const float *W4, const float *W5, const float *Wd,
                         const float *Ws1, u32 *Bw, u32 *Bs1, float *stats)
{
    int b = blockIdx.x, tid = threadIdx.x;
    if (b < 270) {
        int l = b / 54, bb = b % 54;
        const float *Wl = (l == 0) ? W1 : (l == 1) ? W2 : (l == 2) ? W3 : (l == 3) ? W4 : W5;
        prep_w_body(Wl, Bw + (size_t)l * 27 * 512, 27, bb * 256 + tid);
    } else if (b < 286) {
        prep_w_body(Wd, Bw + (size_t)5 * 27 * 512, 8, (b - 270) * 256 + tid);
    } else if (b < 293) {
        int t = (b - 286) * 256 + tid;
        if (t < 1792) {
            int g    = t >> 8;
            int r    = t & 255;
            int c2   = r >> 7;
            int lane = (r >> 2) & 31;
            int e    = r & 3;
            int nc   = c2 * 2 + (e >> 1);
            int h    = e & 1;
            int mm   = lane & 3;
            int n    = nc * 8 + (lane >> 2);
            int k0   = 2 * mm + 8 * h;
            int tap  = 4 * g + (k0 >> 2);
            int ci   = k0 & 3;
            float w0 = (tap < 27) ? Ws1[((size_t)tap * 4 + ci) * 32 + n] : 0.f;
            float w1 = (tap < 27) ? Ws1[((size_t)tap * 4 + ci + 1) * 32 + n] : 0.f;
            Bs1[t] = packh(w0, w1);
        }
    } else {
        for (int i = tid; i < 448; i += 256) stats[i] = 0.f;
    }
}

// ---------------------------------------------------------------------------
// HMMA gather-spconv (2-pass split-fp16). 16 rows/warp, 128 rows/CTA,
// 256 threads. R12 loop shape (64 regs -> 4 CTAs/SM); u32 gather offsets.
// ---------------------------------------------------------------------------
template <int K>
__global__ void __launch_bounds__(256, 3) mma_conv_kernel(
    const u32 *__restrict__ feat,     // split rows [*, 32 u32]
    const int *__restrict__ nbr,      // [K, N]
    const uint4 *__restrict__ Wf,     // fragment weights, K*128 uint4
    float      *__restrict__ out,     // [N, 32] raw pre-BN
    float      *__restrict__ stats,   // [64]
    int N)
{
    extern __shared__ u32 sW[];       // K*512 u32
    __shared__ float s_sum[64];
    const int tid = threadIdx.x, wid = tid >> 5, lane = tid & 31;

    {
        uint4 *dst = (uint4 *)sW;
#pragma unroll 2
        for (int i = tid; i < K * 128; i += 256) dst[i] = __ldg(Wf + i);
    }
    if (tid < 64) s_sum[tid] = 0.f;
    __syncthreads();

    const int rowbase = (blockIdx.x * 8 + wid) * 16;
    const int m = lane & 3;
    const int rq = lane >> 2;
    const int r_lo = rowbase + rq;
    const int r_hi = r_lo + 8;
    const bool v_lo = (r_lo < N), v_hi = (r_hi < N);
    const u32 mo = (u32)m * 16u;
    const char *fb = (const char *)feat;

    float acc[16];
#pragma unroll
    for (int i = 0; i < 16; i++) acc[i] = 0.f;

    const int *nb = nbr;
    int i0 = v_lo ? __ldg(nb + r_lo) : -1;
    int i1 = v_hi ? __ldg(nb + r_hi) : -1;

#pragma unroll 1
    for (int k = 0; k < K; k++) {
        int n0 = -1, n1 = -1;
        if (k + 1 < K) {
            n0 = v_lo ? __ldg(nb + N + r_lo) : -1;
            n1 = v_hi ? __ldg(nb + N + r_hi) : -1;
        }
        if (__ballot_sync(0xffffffffu, (i0 >= 0) | (i1 >= 0))) {
            uint4 H0v, L0v, H1v, L1v;
            if (i0 >= 0) {
                const char *p = fb + (((u32)i0 << 7) + mo);
                H0v = __ldg((const uint4 *)p);
                L0v = __ldg((const uint4 *)(p + 64));
            } else {
                H0v = make_uint4(0u, 0u, 0u, 0u);
                L0v = make_uint4(0u, 0u, 0u, 0u);
            }
            if (i1 >= 0) {
                const char *p = fb + (((u32)i1 << 7) + mo);
                H1v = __ldg((const uint4 *)p);
                L1v = __ldg((const uint4 *)(p + 64));
            } else {
                H1v = make_uint4(0u, 0u, 0u, 0u);
                L1v = make_uint4(0u, 0u, 0u, 0u);
            }
            const u32 hb = (u32)k * 512u;
            {   // kc0
                uint4 W00 = ((const uint4 *)(sW + hb))[lane];
                uint4 W01 = ((const uint4 *)(sW + hb + 128))[lane];
                u32 ah[4] = { H0v.x, H1v.x, H0v.y, H1v.y };
                u32 al[4] = { L0v.x, L1v.x, L0v.y, L1v.y };
                mma_pass2(acc, ah, al, W00, W01);
            }
            {   // kc1
                uint4 W10 = ((const uint4 *)(sW + hb + 256))[lane];
                uint4 W11 = ((const uint4 *)(sW + hb + 384))[lane];
                u32 ah[4] = { H0v.z, H1v.z, H0v.w, H1v.w };
                u32 al[4] = { L0v.z, L1v.z, L0v.w, L1v.w };
                mma_pass2(acc, ah, al, W10, W11);
            }
        }
        i0 = n0; i1 = n1; nb += N;
    }

    // ---- epilogue: store raw rows; cols = nc*8 + m*2
    if (v_lo) {
        float *o = out + (size_t)r_lo * 32 + m * 2;
#pragma unroll
        for (int nc = 0; nc < 4; nc++)
            *(float2 *)(o + nc * 8) = make_float2(acc[nc * 4 + 0], acc[nc * 4 + 1]);
    }
    if (v_hi) {
        float *o = out + (size_t)r_hi * 32 + m * 2;
#pragma unroll
        for (int nc = 0; nc < 4; nc++)
            *(float2 *)(o + nc * 8) = make_float2(acc[nc * 4 + 2], acc[nc * 4 + 3]);
    }

    // ---- BN partial sums (invalid rows hold exact zeros)
#pragma unroll
    for (int nc = 0; nc < 4; nc++) {
#pragma unroll
        for (int j = 0; j < 2; j++) {
            float a0 = acc[nc * 4 + j], a1 = acc[nc * 4 + 2 + j];
            float s = a0 + a1;
            float q = a0 * a0 + a1 * a1;
#pragma unroll
            for (int o = 16; o >= 4; o >>= 1) {
                s += __shfl_xor_sync(0xffffffffu, s, o);
                q += __shfl_xor_sync(0xffffffffu, q, o);
            }
            if (lane < 4) {
                atomicAdd(&s_sum[nc * 8 + 2 * lane + j], s);
                atomicAdd(&s_sum[32 + nc * 8 + 2 * lane + j], q);
            }
        }
    }
    __syncthreads();
    if (tid < 64) atomicAdd(&stats[tid], s_sum[tid]);
}

// ---------------------------------------------------------------------------
// stem1 (acc16 shape): CIN=4 fp32 input, 27 taps as 7 K=16 groups of 4 taps.
// 16 rows/warp, 128 rows/CTA. 2-pass split-fp16 on the fly.
// ---------------------------------------------------------------------------
__global__ void __launch_bounds__(256, 3) stem1_kernel(
    const float *__restrict__ feat, const int *__restrict__ nbr,
    const u32 *__restrict__ Wf, float *__restrict__ out,
    float *__restrict__ stats, int N)
{
    __shared__ u32 sW[1792];
    __shared__ float s_sum[64];
    const int tid = threadIdx.x, wid = tid >> 5, lane = tid & 31;

    for (int i = tid; i < 448; i += 256) ((uint4 *)sW)[i] = __ldg((const uint4 *)Wf + i);
    if (tid < 64) s_sum[tid] = 0.f;
    __syncthreads();

    const int rowbase = (blockIdx.x * 8 + wid) * 16;
    const int m = lane & 3;
    const int rq = lane >> 2;
    const int r_lo = rowbase + rq;
    const int r_hi = r_lo + 8;
    const bool v_lo = (r_lo < N), v_hi = (r_hi < N);
    const int ci0 = (m & 1) * 2;
    const int tA0 = m >> 1;

    float acc[16];
#pragma unroll
    for (int i = 0; i < 16; i++) acc[i] = 0.f;

#pragma unroll 1
    for (int g = 0; g < 7; g++) {
        const int tA = 4 * g + tA0;
        const int tB = tA + 2;
        int iA0 = v_lo ? __ldg(nbr + (size_t)tA * N + r_lo) : -1;
        int iA1 = v_hi ? __ldg(nbr + (size_t)tA * N + r_hi) : -1;
        int iB0 = (v_lo && tB < 27) ? __ldg(nbr + (size_t)tB * N + r_lo) : -1;
        int iB1 = (v_hi && tB < 27) ? __ldg(nbr + (size_t)tB * N + r_hi) : -1;
        float2 fA0 = (iA0 >= 0) ? __ldg((const float2 *)(feat + (size_t)iA0 * 4 + ci0))
                                : make_float2(0.f, 0.f);
        float2 fA1 = (iA1 >= 0) ? __ldg((const float2 *)(feat + (size_t)iA1 * 4 + ci0))
                                : make_float2(0.f, 0.f);
        float2 fB0 = (iB0 >= 0) ? __ldg((const float2 *)(feat + (size_t)iB0 * 4 + ci0))
                                : make_float2(0.f, 0.f);
        float2 fB1 = (iB1 >= 0) ? __ldg((const float2 *)(feat + (size_t)iB1 * 4 + ci0))
                                : make_float2(0.f, 0.f);
        uint4 H0 = ((const uint4 *)(sW + g * 256))[lane];
        uint4 H1 = ((const uint4 *)(sW + g * 256 + 128))[lane];
        u32 ah[4], al[4];
        cvtp(fA0.x, fA0.y, ah[0], al[0]);
        cvtp(fA1.x, fA1.y, ah[1], al[1]);
        cvtp(fB0.x, fB0.y, ah[2], al[2]);
        cvtp(fB1.x, fB1.y, ah[3], al[3]);
        mma_pass2(acc, ah, al, H0, H1);
    }

    // epilogue
    if (v_lo) {
        float *o = out + (size_t)r_lo * 32 + m * 2;
#pragma unroll
        for (int nc = 0; nc < 4; nc++)
            *(float2 *)(o + nc * 8) = make_float2(acc[nc * 4 + 0], acc[nc * 4 + 1]);
    }
    if (v_hi) {
        float *o = out + (size_t)r_hi * 32 + m * 2;
#pragma unroll
        for (int nc = 0; nc < 4; nc++)
            *(float2 *)(o + nc * 8) = make_float2(acc[nc * 4 + 2], acc[nc * 4 + 3]);
    }
#pragma unroll
    for (int nc = 0; nc < 4; nc++) {
#pragma unroll
        for (int j = 0; j < 2; j++) {
            float a0 = acc[nc * 4 + j], a1 = acc[nc * 4 + 2 + j];
            float s = a0 + a1;
            float q = a0 * a0 + a1 * a1;
#pragma unroll
            for (int o = 16; o >= 4; o >>= 1) {
                s += __shfl_xor_sync(0xffffffffu, s, o);
                q += __shfl_xor_sync(0xffffffffu, q, o);
            }
            if (lane < 4) {
                atomicAdd(&s_sum[nc * 8 + 2 * lane + j], s);
                atomicAdd(&s_sum[32 + nc * 8 + 2 * lane + j], q);
            }
        }
    }
    __syncthreads();
    if (tid < 64) atomicAdd(&stats[tid], s_sum[tid]);
}

// ---------------------------------------------------------------------------
// applies (finalize fused per-CTA); split format fp16 pairs
// ---------------------------------------------------------------------------
__global__ void apply_split(const float *__restrict__ x,
                            const float *__restrict__ stats,
                            const float *__restrict__ g, const float *__restrict__ b,
                            float invN, u32 *__restrict__ out, int n)
{
    __shared__ float ssm[64];
    int tid = threadIdx.x;
    if (tid < 32) compute_ss(ssm, stats, g, b, invN, tid);
    __syncthreads();
    int i = blockIdx.x * blockDim.x + tid;
    if (i >= n) return;
    int row = i >> 2, m = i & 3;
    const float4 *px = (const float4 *)(x + (size_t)row * 32 + m * 8);
    float4 v0 = __ldg(px), v1 = __ldg(px + 1);
    float4 sc0 = *(float4 *)(ssm + 8 * m), sc1 = *(float4 *)(ssm + 8 * m + 4);
    float4 sh0 = *(float4 *)(ssm + 32 + 8 * m), sh1 = *(float4 *)(ssm + 32 + 8 * m + 4);
    float o0 = fmaxf(fmaf(v0.x, sc0.x, sh0.x), 0.f);
    float o1 = fmaxf(fmaf(v0.y, sc0.y, sh0.y), 0.f);
    float o2 = fmaxf(fmaf(v0.z, sc0.z, sh0.z), 0.f);
    float o3 = fmaxf(fmaf(v0.w, sc0.w, sh0.w), 0.f);
    float o4 = fmaxf(fmaf(v1.x, sc1.x, sh1.x), 0.f);
    float o5 = fmaxf(fmaf(v1.y, sc1.y, sh1.y), 0.f);
    float o6 = fmaxf(fmaf(v1.z, sc1.z, sh1.z), 0.f);
    float o7 = fmaxf(fmaf(v1.w, sc1.w, sh1.w), 0.f);
    uint4 h, l;
    cvtp(o0, o1, h.x, l.x);
    cvtp(o2, o3, h.y, l.y);
    cvtp(o4, o5, h.z, l.z);
    cvtp(o6, o7, h.w, l.w);
    uint4 *po = (uint4 *)(out + (size_t)row * 32);
    po[m] = h;
    po[4 + m] = l;
}

// x1' = relu( bn(h_raw) + res(split) ) -> split
__global__ void apply_res(const float *__restrict__ h,
                          const float *__restrict__ stats,
                          const float *__restrict__ g, const float *__restrict__ b,
                          const u32 *__restrict__ res,
                          float invN, u32 *__restrict__ out, int n)
{
    __shared__ float ssm[64];
    int tid = threadIdx.x;
    if (tid < 32) compute_ss(ssm, stats, g, b, invN, tid);
    __syncthreads();
    int i = blockIdx.x * blockDim.x + tid;
    if (i >= n) return;
    int row = i >> 2, m = i & 3;
    const float4 *ph = (const float4 *)(h + (size_t)row * 32 + m * 8);
    float4 h0 = __ldg(ph), h1 = __ldg(ph + 1);
    float4 sc0 = *(float4 *)(ssm + 8 * m), sc1 = *(float4 *)(ssm + 8 * m + 4);
    float4 sh0 = *(float4 *)(ssm + 32 + 8 * m), sh1 = *(float4 *)(ssm + 32 + 8 * m + 4);
    const uint4 *pr = (const uint4 *)(res + (size_t)row * 32);
    uint4 rh = __ldg(pr + m), rl = __ldg(pr + 4 + m);
    float2 vx = unph(rh.x), wx = unph(rl.x);
    float2 vy = unph(rh.y), wy = unph(rl.y);
    float2 vz = unph(rh.z), wz = unph(rl.z);
    float2 vw = unph(rh.w), ww = unph(rl.w);
    float o0 = fmaxf(fmaf(h0.x, sc0.x, sh0.x) + vx.x + wx.x, 0.f);
    float o1 = fmaxf(fmaf(h0.y, sc0.y, sh0.y) + vx.y + wx.y, 0.f);
    float o2 = fmaxf(fmaf(h0.z, sc0.z, sh0.z) + vy.x + wy.x, 0.f);
    float o3 = fmaxf(fmaf(h0.w, sc0.w, sh0.w) + vy.y + wy.y, 0.f);
    float o4 = fmaxf(fmaf(h1.x, sc1.x, sh1.x) + vz.x + wz.x, 0.f);
    float o5 = fmaxf(fmaf(h1.y, sc1.y, sh1.y) + vz.y + wz.y, 0.f);
    float o6 = fmaxf(fmaf(h1.z, sc1.z, sh1.z) + vw.x + ww.x, 0.f);
    float o7 = fmaxf(fmaf(h1.w, sc1.w, sh1.w) + vw.y + ww.y, 0.f);
    uint4 hh, ll;
    cvtp(o0, o1, hh.x, ll.x);
    cvtp(o2, o3, hh.y, ll.y);
    cvtp(o4, o5, hh.z, ll.z);
    cvtp(o6, o7, hh.w, ll.w);
    uint4 *po = (uint4 *)(out + (size_t)row * 32);
    po[m] = hh;
    po[4 + m] = ll;
}

// out = relu( bn(h_raw) + res(split) ) -> fp32 natural order
__global__ void apply_final(const float *__restrict__ h,
                            const float *__restrict__ stats,
                            const float *__restrict__ g, const float *__restrict__ b,
                            const u32 *__restrict__ res,
                            float invN, float *__restrict__ out, int n)
{
    __shared__ float ssm[64];
    int tid = threadIdx.x;
    if (tid < 32) compute_ss(ssm, stats, g, b, invN, tid);
    __syncthreads();
    int i = blockIdx.x * blockDim.x + tid;
    if (i >= n) return;
    int row = i >> 2, m = i & 3;
    const float4 *ph = (const float4 *)(h + (size_t)row * 32 + m * 8);
    float4 h0 = __ldg(ph), h1 = __ldg(ph + 1);
    float4 sc0 = *(float4 *)(ssm + 8 * m), sc1 = *(float4 *)(ssm + 8 * m + 4);
    float4 sh0 = *(float4 *)(ssm + 32 + 8 * m), sh1 = *(float4 *)(ssm + 32 + 8 * m + 4);
    const uint4 *pr = (const uint4 *)(res + (size_t)row * 32);
    uint4 rh = __ldg(pr + m), rl = __ldg(pr + 4 + m);
    float2 vx = unph(rh.x), wx = unph(rl.x);
    float2 vy = unph(rh.y), wy = unph(rl.y);
    float2 vz = unph(rh.z), wz = unph(rl.z);
    float2 vw = unph(rh.w), ww = unph(rl.w);
    float4 a, bb;
    a.x  = fmaxf(fmaf(h0.x, sc0.x, sh0.x) + vx.x + wx.x, 0.f);
    a.y  = fmaxf(fmaf(h0.y, sc0.y, sh0.y) + vx.y + wx.y, 0.f);
    a.z  = fmaxf(fmaf(h0.z, sc0.z, sh0.z) + vy.x + wy.x, 0.f);
    a.w  = fmaxf(fmaf(h0.w, sc0.w, sh0.w) + vy.y + wy.y, 0.f);
    bb.x = fmaxf(fmaf(h1.x, sc1.x, sh1.x) + vz.x + wz.x, 0.f);
    bb.y = fmaxf(fmaf(h1.y, sc1.y, sh1.y) + vz.y + wz.y, 0.f);
    bb.z = fmaxf(fmaf(h1.z, sc1.z, sh1.z) + vw.x + ww.x, 0.f);
    bb.w = fmaxf(fmaf(h1.w, sc1.w, sh1.w) + vw.y + ww.y, 0.f);
    float4 *po = (float4 *)(out + (size_t)row * 32 + m * 8);
    po[0] = a;
    po[1] = bb;
}

// ---------------------------------------------------------------------------
extern "C" void kernel_launch(void *const *d_in, const int *in_sizes, int n_in,
                              void *d_out, int out_size)
{
    const float *vf     = (const float *)d_in[0];
    const float *Wstem1 = (const float *)d_in[1];
    const float *Wstem2 = (const float *)d_in[2];
    const float *Wdown  = (const float *)d_in[3];
    const float *Wr1a   = (const float *)d_in[4];
    const float *Wr1b   = (const float *)d_in[5];
    const float *Wr2a   = (const float *)d_in[6];
    const float *Wr2b   = (const float *)d_in[7];
    const float *gam    = (const float *)d_in[8];
    const float *bet    = (const float *)d_in[9];
    const int *nbr0  = (const int *)d_in[10];
    const int *down1 = (const int *)d_in[11];
    const int *nbr1  = (const int *)d_in[12];

    int N0 = in_sizes[10] / 27;
    int N1 = in_sizes[11] / 8;

    float *bufA, *bufB, *bufC, *bufD, *stats;
    u32 *Bw, *Bs1;
    cudaGetSymbolAddress((void **)&bufA, g_bufA);
    cudaGetSymbolAddress((void **)&bufB, g_bufB);
    cudaGetSymbolAddress((void **)&bufC, g_bufC);
    cudaGetSymbolAddress((void **)&bufD, g_bufD);
    cudaGetSymbolAddress((void **)&stats, g_stats);
    cudaGetSymbolAddress((void **)&Bw, g_Bw);
    cudaGetSymbolAddress((void **)&Bs1, g_Bs1);

    u32 *uA = (u32 *)bufA, *uB = (u32 *)bufB, *uC = (u32 *)bufC, *uD = (u32 *)bufD;

    const size_t L27 = (size_t)27 * 512;
    u32 *B_stem2 = Bw + 0 * L27;
    u32 *B_r1a   = Bw + 1 * L27;
    u32 *B_r1b   = Bw + 2 * L27;
    u32 *B_r2a   = Bw + 3 * L27;
    u32 *B_r2b   = Bw + 4 * L27;
    u32 *B_down  = Bw + 5 * L27;

    size_t sm27 = (size_t)27 * 2048;   // 55296 B
    size_t sm8  = (size_t)8 * 2048;    // 16384 B
    cudaFuncSetAttribute(mma_conv_kernel<27>,
                         cudaFuncAttributeMaxDynamicSharedMemorySize, (int)sm27);
    cudaFuncSetAttribute(mma_conv_kernel<8>,
                         cudaFuncAttributeMaxDynamicSharedMemorySize, (int)sm8);

    int g0  = (N0 + 127) / 128;   // 128 rows per CTA
    int g1  = (N1 + 127) / 128;
    int a0n = (N0 * 4 + 255) / 256;
    int a1n = (N1 * 4 + 255) / 256;
    float invN0 = 1.f / (float)N0;
    float invN1 = 1.f / (float)N1;
    float *out = (float *)d_out;

    prep_all<<<294, 256>>>(Wstem2, Wr1a, Wr1b, Wr2a, Wr2b, Wdown, Wstem1, Bw, Bs1, stats);

    // stem1: vf -> raw A + stats0; apply -> split B
    stem1_kernel<<<g0, 256>>>(vf, nbr0, Bs1, bufA, stats + 0, N0);
    apply_split<<<a0n, 256>>>(bufA, stats + 0, gam + 0, bet + 0, invN0, uB, N0 * 4);

    // stem2: split B -> raw C + stats1; apply -> split A
    mma_conv_kernel<27><<<g0, 256, sm27>>>(uB, nbr0, (const uint4 *)B_stem2, bufC, stats + 64, N0);
    apply_split<<<a0n, 256>>>(bufC, stats + 64, gam + 32, bet + 32, invN0, uA, N0 * 4);

    // down: split A (level0) -> raw C + stats2; apply -> split D (= x1)
    mma_conv_kernel<8><<<g1, 256, sm8>>>(uA, down1, (const uint4 *)B_down, bufC, stats + 128, N1);
    apply_split<<<a1n, 256>>>(bufC, stats + 128, gam + 64, bet + 64, invN1, uD, N1 * 4);

    // r1a: split D -> raw A + stats3; apply -> split B
    mma_conv_kernel<27><<<g1, 256, sm27>>>(uD, nbr1, (const uint4 *)B_r1a, bufA, stats + 192, N1);
    apply_split<<<a1n, 256>>>(bufA, stats + 192, gam + 96, bet + 96, invN1, uB, N1 * 4);

    // r1b: split B -> raw A + stats4; res join with D -> split C (= x1')
    mma_conv_kernel<27><<<g1, 256, sm27>>>(uB, nbr1, (const uint4 *)B_r1b, bufA, stats + 256, N1);
    apply_res<<<a1n, 256>>>(bufA, stats + 256, gam + 128, bet + 128, uD, invN1, uC, N1 * 4);

    // r2a: split C -> raw A + stats5; apply -> split B
    mma_conv_kernel<27><<<g1, 256, sm27>>>(uC, nbr1, (const uint4 *)B_r2a, bufA, stats + 320, N1);
    apply_split<<<a1n, 256>>>(bufA, stats + 320, gam + 160, bet + 160, invN1, uB, N1 * 4);

    // r2b: split B -> raw A + stats6; final join with C -> fp32 out
    mma_conv_kernel<27><<<g1, 256, sm27>>>(uB, nbr1, (const uint4 *)B_r2b, bufA, stats + 384, N1);
    apply_final<<<a1n, 256>>>(bufA, stats + 384, gam + 192, bet + 192, uC, invN1, out, N1 * 4);
}

// round 16
// speedup vs baseline: 1.1204x; 1.1204x over previous
#include <cuda_runtime.h>
#include <cuda_fp16.h>
#include <cstdint>

typedef unsigned long long u64;
typedef unsigned int u32;

// ---------------------------------------------------------------------------
// Scratch (no allocations allowed). Activation buffers hold either raw fp32
// rows or split-fp16 rows (u32[32]: 16 hi pairs + 16 lo pairs) — same bytes.
// ---------------------------------------------------------------------------
#define MAXN 450000
__device__ float g_bufA[(size_t)MAXN * 32];
__device__ float g_bufB[(size_t)MAXN * 32];
__device__ float g_bufC[(size_t)MAXN * 32];
__device__ float g_bufD[(size_t)MAXN * 32];
__device__ float g_stats[7 * 64];   // per layer: sum[32], sumsq[32]
__device__ u32 g_Bw[5 * 27 * 512 + 8 * 512];   // single-fp16 fragment weights
__device__ u32 g_Bs1[1792];

// ---------------------------------------------------------------------------
// helpers
// ---------------------------------------------------------------------------
__device__ __forceinline__ u32 packh(float x, float y) {
    __half2 h = __floats2half2_rn(x, y);
    return *(u32 *)&h;
}
__device__ __forceinline__ float2 unph(u32 u) {
    __half2 h = *(__half2 *)&u;
    return __half22float2(h);
}
__device__ __forceinline__ void cvtp(float x, float y, u32 &h, u32 &l) {
    h = packh(x, y);
    float2 r = unph(h);
    l = packh(x - r.x, y - r.y);
}
__device__ __forceinline__ void mma16816(float *d, const u32 *a, u32 b0, u32 b1) {
    asm volatile(
        "mma.sync.aligned.m16n8k16.row.col.f32.f16.f16.f32 "
        "{%0,%1,%2,%3}, {%4,%5,%6,%7}, {%8,%9}, {%0,%1,%2,%3};"
        : "+f"(d[0]), "+f"(d[1]), "+f"(d[2]), "+f"(d[3])
        : "r"(a[0]), "r"(a[1]), "r"(a[2]), "r"(a[3]), "r"(b0), "r"(b1));
}
// 8 MMAs: 2 passes (ah, al) x 4 nc against single-fp16 weights
__device__ __forceinline__ void mma_pass2(float *acc, const u32 *ah, const u32 *al,
                                          uint4 H0, uint4 H1) {
    mma16816(acc + 0,  ah, H0.x, H0.y);
    mma16816(acc + 0,  al, H0.x, H0.y);
    mma16816(acc + 4,  ah, H0.z, H0.w);
    mma16816(acc + 4,  al, H0.z, H0.w);
    mma16816(acc + 8,  ah, H1.x, H1.y);
    mma16816(acc + 8,  al, H1.x, H1.y);
    mma16816(acc + 12, ah, H1.z, H1.w);
    mma16816(acc + 12, al, H1.z, H1.w);
}
// BN scale/shift into smem (first 32 threads)
__device__ __forceinline__ void compute_ss(float *ssm, const float *stats,
                                           const float *gamma, const float *beta,
                                           float invN, int c) {
    float mu  = stats[c] * invN;
    float var = stats[32 + c] * invN - mu * mu;
    float sc = rsqrtf(var + 1e-5f) * gamma[c];
    ssm[c] = sc;
    ssm[32 + c] = beta[c] - mu * sc;
}

// ---------------------------------------------------------------------------
// Combined weight prep + stats zero (1 launch); fp16 single-precision weights.
// ---------------------------------------------------------------------------
__device__ void prep_w_body(const float *__restrict__ W, u32 *__restrict__ out,
                            int K, int t)
{
    if (t >= K * 512) return;
    int tap  = t >> 9;
    int r    = t & 511;
    int kc   = r >> 8;
    int c2   = (r >> 7) & 1;
    int lane = (r >> 2) & 31;
    int e    = r & 3;
    int nc   = c2 * 2 + (e >> 1);
    int h    = e & 1;
    int mm   = lane & 3;
    int n    = nc * 8 + (lane >> 2);
    int k0   = 8 * mm + 4 * kc + 2 * h;
    float w0 = W[((size_t)tap * 32 + k0) * 32 + n];
    float w1 = W[((size_t)tap * 32 + k0 + 1) * 32 + n];
    out[t] = packh(w0, w1);
}

__global__ void prep_all(const float *W1, const float *W2, const float *W3,
                         const float *W4, const float *W5, const float *Wd,
                         const float *Ws1, u32 *Bw, u32 *Bs1, float *stats)
{
    int b = blockIdx.x, tid = threadIdx.x;
    if (b < 270) {
        int l = b / 54, bb = b % 54;
        const float *Wl = (l == 0) ? W1 : (l == 1) ? W2 : (l == 2) ? W3 : (l == 3) ? W4 : W5;
        prep_w_body(Wl, Bw + (size_t)l * 27 * 512, 27, bb * 256 + tid);
    } else if (b < 286) {
        prep_w_body(Wd, Bw + (size_t)5 * 27 * 512, 8, (b - 270) * 256 + tid);
    } else if (b < 293) {
        int t = (b - 286) * 256 + tid;
        if (t < 1792) {
            int g    = t >> 8;
            int r    = t & 255;
            int c2   = r >> 7;
            int lane = (r >> 2) & 31;
            int e    = r & 3;
            int nc   = c2 * 2 + (e >> 1);
            int h    = e & 1;
            int mm   = lane & 3;
            int n    = nc * 8 + (lane >> 2);
            int k0   = 2 * mm + 8 * h;
            int tap  = 4 * g + (k0 >> 2);
            int ci   = k0 & 3;
            float w0 = (tap < 27) ? Ws1[((size_t)tap * 4 + ci) * 32 + n] : 0.f;
            float w1 = (tap < 27) ? Ws1[((size_t)tap * 4 + ci + 1) * 32 + n] : 0.f;
            Bs1[t] = packh(w0, w1);
        }
    } else {
        for (int i = tid; i < 448; i += 256) stats[i] = 0.f;
    }
}

// ---------------------------------------------------------------------------
// HMMA gather-spconv (2-pass split-fp16). 16 rows/warp, 128 rows/CTA,
// 256 threads, 3 CTAs/SM target (24 warps). Weights in smem, kc halves.
// EXACT R12 loop shape (measured 64 regs -> 4 CTAs/SM).
// ---------------------------------------------------------------------------
template <int K>
__global__ void __launch_bounds__(256, 3) mma_conv_kernel(
    const u32 *__restrict__ feat,     // split rows [*, 32 u32]
    const int *__restrict__ nbr,      // [K, N]
    const uint4 *__restrict__ Wf,     // fragment weights, K*128 uint4
    float      *__restrict__ out,     // [N, 32] raw pre-BN
    float      *__restrict__ stats,   // [64]
    int N)
{
    extern __shared__ u32 sW[];       // K*512 u32
    __shared__ float s_sum[64];
    const int tid = threadIdx.x, wid = tid >> 5, lane = tid & 31;

    {
        uint4 *dst = (uint4 *)sW;
#pragma unroll 2
        for (int i = tid; i < K * 128; i += 256) dst[i] = __ldg(Wf + i);
    }
    if (tid < 64) s_sum[tid] = 0.f;
    __syncthreads();

    const int rowbase = (blockIdx.x * 8 + wid) * 16;
    const int m = lane & 3;
    const int rq = lane >> 2;
    const int r_lo = rowbase + rq;
    const int r_hi = r_lo + 8;
    const bool v_lo = (r_lo < N), v_hi = (r_hi < N);

    float acc[16];
#pragma unroll
    for (int i = 0; i < 16; i++) acc[i] = 0.f;

    const int *nb = nbr;
    int i0 = v_lo ? __ldg(nb + r_lo) : -1;
    int i1 = v_hi ? __ldg(nb + r_hi) : -1;

#pragma unroll 1
    for (int k = 0; k < K; k++) {
        int n0 = -1, n1 = -1;
        if (k + 1 < K) {
            n0 = v_lo ? __ldg(nb + N + r_lo) : -1;
            n1 = v_hi ? __ldg(nb + N + r_hi) : -1;
        }
        if (__ballot_sync(0xffffffffu, (i0 >= 0) | (i1 >= 0))) {
            uint4 H0v, L0v, H1v, L1v;
            if (i0 >= 0) {
                const uint4 *p = (const uint4 *)(feat + (size_t)i0 * 32);
                H0v = __ldg(p + m);
                L0v = __ldg(p + 4 + m);
            } else {
                H0v = make_uint4(0u, 0u, 0u, 0u);
                L0v = make_uint4(0u, 0u, 0u, 0u);
            }
            if (i1 >= 0) {
                const uint4 *p = (const uint4 *)(feat + (size_t)i1 * 32);
                H1v = __ldg(p + m);
                L1v = __ldg(p + 4 + m);
            } else {
                H1v = make_uint4(0u, 0u, 0u, 0u);
                L1v = make_uint4(0u, 0u, 0u, 0u);
            }
            const u32 hb = (u32)k * 512u;
            {   // kc0
                uint4 W00 = ((const uint4 *)(sW + hb))[lane];
                uint4 W01 = ((const uint4 *)(sW + hb + 128))[lane];
                u32 ah[4] = { H0v.x, H1v.x, H0v.y, H1v.y };
                u32 al[4] = { L0v.x, L1v.x, L0v.y, L1v.y };
                mma_pass2(acc, ah, al, W00, W01);
            }
            {   // kc1
                uint4 W10 = ((const uint4 *)(sW + hb + 256))[lane];
                uint4 W11 = ((const uint4 *)(sW + hb + 384))[lane];
                u32 ah[4] = { H0v.z, H1v.z, H0v.w, H1v.w };
                u32 al[4] = { L0v.z, L1v.z, L0v.w, L1v.w };
                mma_pass2(acc, ah, al, W10, W11);
            }
        }
        i0 = n0; i1 = n1; nb += N;
    }

    // ---- epilogue: store raw rows; cols = nc*8 + m*2
    if (v_lo) {
        float *o = out + (size_t)r_lo * 32 + m * 2;
#pragma unroll
        for (int nc = 0; nc < 4; nc++)
            *(float2 *)(o + nc * 8) = make_float2(acc[nc * 4 + 0], acc[nc * 4 + 1]);
    }
    if (v_hi) {
        float *o = out + (size_t)r_hi * 32 + m * 2;
#pragma unroll
        for (int nc = 0; nc < 4; nc++)
            *(float2 *)(o + nc * 8) = make_float2(acc[nc * 4 + 2], acc[nc * 4 + 3]);
    }

    // ---- BN partial sums (invalid rows hold exact zeros)
#pragma unroll
    for (int nc = 0; nc < 4; nc++) {
#pragma unroll
        for (int j = 0; j < 2; j++) {
            float a0 = acc[nc * 4 + j], a1 = acc[nc * 4 + 2 + j];
            float s = a0 + a1;
            float q = a0 * a0 + a1 * a1;
#pragma unroll
            for (int o = 16; o >= 4; o >>= 1) {
                s += __shfl_xor_sync(0xffffffffu, s, o);
                q += __shfl_xor_sync(0xffffffffu, q, o);
            }
            if (lane < 4) {
                atomicAdd(&s_sum[nc * 8 + 2 * lane + j], s);
                atomicAdd(&s_sum[32 + nc * 8 + 2 * lane + j], q);
            }
        }
    }
    __syncthreads();
    if (tid < 64) atomicAdd(&stats[tid], s_sum[tid]);
}

// ---------------------------------------------------------------------------
// stem1 (acc16 shape): CIN=4 fp32 input, 27 taps as 7 K=16 groups of 4 taps.
// 16 rows/warp, 128 rows/CTA. 2-pass split-fp16 on the fly.
// ---------------------------------------------------------------------------
__global__ void __launch_bounds__(256, 3) stem1_kernel(
    const float *__restrict__ feat, const int *__restrict__ nbr,
    const u32 *__restrict__ Wf, float *__restrict__ out,
    float *__restrict__ stats, int N)
{
    __shared__ u32 sW[1792];
    __shared__ float s_sum[64];
    const int tid = threadIdx.x, wid = tid >> 5, lane = tid & 31;

    for (int i = tid; i < 448; i += 256) ((uint4 *)sW)[i] = __ldg((const uint4 *)Wf + i);
    if (tid < 64) s_sum[tid] = 0.f;
    __syncthreads();

    const int rowbase = (blockIdx.x * 8 + wid) * 16;
    const int m = lane & 3;
    const int rq = lane >> 2;
    const int r_lo = rowbase + rq;
    const int r_hi = r_lo + 8;
    const bool v_lo = (r_lo < N), v_hi = (r_hi < N);
    const int ci0 = (m & 1) * 2;
    const int tA0 = m >> 1;

    float acc[16];
#pragma unroll
    for (int i = 0; i < 16; i++) acc[i] = 0.f;

#pragma unroll 1
    for (int g = 0; g < 7; g++) {
        const int tA = 4 * g + tA0;
        const int tB = tA + 2;
        int iA0 = v_lo ? __ldg(nbr + (size_t)tA * N + r_lo) : -1;
        int iA1 = v_hi ? __ldg(nbr + (size_t)tA * N + r_hi) : -1;
        int iB0 = (v_lo && tB < 27) ? __ldg(nbr + (size_t)tB * N + r_lo) : -1;
        int iB1 = (v_hi && tB < 27) ? __ldg(nbr + (size_t)tB * N + r_hi) : -1;
        float2 fA0 = (iA0 >= 0) ? __ldg((const float2 *)(feat + (size_t)iA0 * 4 + ci0))
                                : make_float2(0.f, 0.f);
        float2 fA1 = (iA1 >= 0) ? __ldg((const float2 *)(feat + (size_t)iA1 * 4 + ci0))
                                : make_float2(0.f, 0.f);
        float2 fB0 = (iB0 >= 0) ? __ldg((const float2 *)(feat + (size_t)iB0 * 4 + ci0))
                                : make_float2(0.f, 0.f);
        float2 fB1 = (iB1 >= 0) ? __ldg((const float2 *)(feat + (size_t)iB1 * 4 + ci0))
                                : make_float2(0.f, 0.f);
        uint4 H0 = ((const uint4 *)(sW + g * 256))[lane];
        uint4 H1 = ((const uint4 *)(sW + g * 256 + 128))[lane];
        u32 ah[4], al[4];
        cvtp(fA0.x, fA0.y, ah[0], al[0]);
        cvtp(fA1.x, fA1.y, ah[1], al[1]);
        cvtp(fB0.x, fB0.y, ah[2], al[2]);
        cvtp(fB1.x, fB1.y, ah[3], al[3]);
        mma_pass2(acc, ah, al, H0, H1);
    }

    // epilogue
    if (v_lo) {
        float *o = out + (size_t)r_lo * 32 + m * 2;
#pragma unroll
        for (int nc = 0; nc < 4; nc++)
            *(float2 *)(o + nc * 8) = make_float2(acc[nc * 4 + 0], acc[nc * 4 + 1]);
    }
    if (v_hi) {
        float *o = out + (size_t)r_hi * 32 + m * 2;
#pragma unroll
        for (int nc = 0; nc < 4; nc++)
            *(float2 *)(o + nc * 8) = make_float2(acc[nc * 4 + 2], acc[nc * 4 + 3]);
    }
#pragma unroll
    for (int nc = 0; nc < 4; nc++) {
#pragma unroll
        for (int j = 0; j < 2; j++) {
            float a0 = acc[nc * 4 + j], a1 = acc[nc * 4 + 2 + j];
            float s = a0 + a1;
            float q = a0 * a0 + a1 * a1;
#pragma unroll
            for (int o = 16; o >= 4; o >>= 1) {
                s += __shfl_xor_sync(0xffffffffu, s, o);
                q += __shfl_xor_sync(0xffffffffu, q, o);
            }
            if (lane < 4) {
                atomicAdd(&s_sum[nc * 8 + 2 * lane + j], s);
                atomicAdd(&s_sum[32 + nc * 8 + 2 * lane + j], q);
            }
        }
    }
    __syncthreads();
    if (tid < 64) atomicAdd(&stats[tid], s_sum[tid]);
}

// ---------------------------------------------------------------------------
// applies (finalize fused per-CTA); split format fp16 pairs
// ---------------------------------------------------------------------------
__global__ void apply_split(const float *__restrict__ x,
                            const float *__restrict__ stats,
                            const float *__restrict__ g, const float *__restrict__ b,
                            float invN, u32 *__restrict__ out, int n)
{
    __shared__ float ssm[64];
    int tid = threadIdx.x;
    if (tid < 32) compute_ss(ssm, stats, g, b, invN, tid);
    __syncthreads();
    int i = blockIdx.x * blockDim.x + tid;
    if (i >= n) return;
    int row = i >> 2, m = i & 3;
    const float4 *px = (const float4 *)(x + (size_t)row * 32 + m * 8);
    float4 v0 = __ldg(px), v1 = __ldg(px + 1);
    float4 sc0 = *(float4 *)(ssm + 8 * m), sc1 = *(float4 *)(ssm + 8 * m + 4);
    float4 sh0 = *(float4 *)(ssm + 32 + 8 * m), sh1 = *(float4 *)(ssm + 32 + 8 * m + 4);
    float o0 = fmaxf(fmaf(v0.x, sc0.x, sh0.x), 0.f);
    float o1 = fmaxf(fmaf(v0.y, sc0.y, sh0.y), 0.f);
    float o2 = fmaxf(fmaf(v0.z, sc0.z, sh0.z), 0.f);
    float o3 = fmaxf(fmaf(v0.w, sc0.w, sh0.w), 0.f);
    float o4 = fmaxf(fmaf(v1.x, sc1.x, sh1.x), 0.f);
    float o5 = fmaxf(fmaf(v1.y, sc1.y, sh1.y), 0.f);
    float o6 = fmaxf(fmaf(v1.z, sc1.z, sh1.z), 0.f);
    float o7 = fmaxf(fmaf(v1.w, sc1.w, sh1.w), 0.f);
    uint4 h, l;
    cvtp(o0, o1, h.x, l.x);
    cvtp(o2, o3, h.y, l.y);
    cvtp(o4, o5, h.z, l.z);
    cvtp(o6, o7, h.w, l.w);
    uint4 *po = (uint4 *)(out + (size_t)row * 32);
    po[m] = h;
    po[4 + m] = l;
}

// x1' = relu( bn(h_raw) + res(split) ) -> split
__global__ void apply_res(const float *__restrict__ h,
                          const float *__restrict__ stats,
                          const float *__restrict__ g, const float *__restrict__ b,
                          const u32 *__restrict__ res,
                          float invN, u32 *__restrict__ out, int n)
{
    __shared__ float ssm[64];
    int tid = threadIdx.x;
    if (tid < 32) compute_ss(ssm, stats, g, b, invN, tid);
    __syncthreads();
    int i = blockIdx.x * blockDim.x + tid;
    if (i >= n) return;
    int row = i >> 2, m = i & 3;
    const float4 *ph = (const float4 *)(h + (size_t)row * 32 + m * 8);
    float4 h0 = __ldg(ph), h1 = __ldg(ph + 1);
    float4 sc0 = *(float4 *)(ssm + 8 * m), sc1 = *(float4 *)(ssm + 8 * m + 4);
    float4 sh0 = *(float4 *)(ssm + 32 + 8 * m), sh1 = *(float4 *)(ssm + 32 + 8 * m + 4);
    const uint4 *pr = (const uint4 *)(res + (size_t)row * 32);
    uint4 rh = __ldg(pr + m), rl = __ldg(pr + 4 + m);
    float2 vx = unph(rh.x), wx = unph(rl.x);
    float2 vy = unph(rh.y), wy = unph(rl.y);
    float2 vz = unph(rh.z), wz = unph(rl.z);
    float2 vw = unph(rh.w), ww = unph(rl.w);
    float o0 = fmaxf(fmaf(h0.x, sc0.x, sh0.x) + vx.x + wx.x, 0.f);
    float o1 = fmaxf(fmaf(h0.y, sc0.y, sh0.y) + vx.y + wx.y, 0.f);
    float o2 = fmaxf(fmaf(h0.z, sc0.z, sh0.z) + vy.x + wy.x, 0.f);
    float o3 = fmaxf(fmaf(h0.w, sc0.w, sh0.w) + vy.y + wy.y, 0.f);
    float o4 = fmaxf(fmaf(h1.x, sc1.x, sh1.x) + vz.x + wz.x, 0.f);
    float o5 = fmaxf(fmaf(h1.y, sc1.y, sh1.y) + vz.y + wz.y, 0.f);
    float o6 = fmaxf(fmaf(h1.z, sc1.z, sh1.z) + vw.x + ww.x, 0.f);
    float o7 = fmaxf(fmaf(h1.w, sc1.w, sh1.w) + vw.y + ww.y, 0.f);
    uint4 hh, ll;
    cvtp(o0, o1, hh.x, ll.x);
    cvtp(o2, o3, hh.y, ll.y);
    cvtp(o4, o5, hh.z, ll.z);
    cvtp(o6, o7, hh.w, ll.w);
    uint4 *po = (uint4 *)(out + (size_t)row * 32);
    po[m] = hh;
    po[4 + m] = ll;
}

// out = relu( bn(h_raw) + res(split) ) -> fp32 natural order
__global__ void apply_final(const float *__restrict__ h,
                            const float *__restrict__ stats,
                            const float *__restrict__ g, const float *__restrict__ b,
                            const u32 *__restrict__ res,
                            float invN, float *__restrict__ out, int n)
{
    __shared__ float ssm[64];
    int tid = threadIdx.x;
    if (tid < 32) compute_ss(ssm, stats, g, b, invN, tid);
    __syncthreads();
    int i = blockIdx.x * blockDim.x + tid;
    if (i >= n) return;
    int row = i >> 2, m = i & 3;
    const float4 *ph = (const float4 *)(h + (size_t)row * 32 + m * 8);
    float4 h0 = __ldg(ph), h1 = __ldg(ph + 1);
    float4 sc0 = *(float4 *)(ssm + 8 * m), sc1 = *(float4 *)(ssm + 8 * m + 4);
    float4 sh0 = *(float4 *)(ssm + 32 + 8 * m), sh1 = *(float4 *)(ssm + 32 + 8 * m + 4);
    const uint4 *pr = (const uint4 *)(res + (size_t)row * 32);
    uint4 rh = __ldg(pr + m), rl = __ldg(pr + 4 + m);
    float2 vx = unph(rh.x), wx = unph(rl.x);
    float2 vy = unph(rh.y), wy = unph(rl.y);
    float2 vz = unph(rh.z), wz = unph(rl.z);
    float2 vw = unph(rh.w), ww = unph(rl.w);
    float4 a, bb;
    a.x  = fmaxf(fmaf(h0.x, sc0.x, sh0.x) + vx.x + wx.x, 0.f);
    a.y  = fmaxf(fmaf(h0.y, sc0.y, sh0.y) + vx.y + wx.y, 0.f);
    a.z  = fmaxf(fmaf(h0.z, sc0.z, sh0.z) + vy.x + wy.x, 0.f);
    a.w  = fmaxf(fmaf(h0.w, sc0.w, sh0.w) + vy.y + wy.y, 0.f);
    bb.x = fmaxf(fmaf(h1.x, sc1.x, sh1.x) + vz.x + wz.x, 0.f);
    bb.y = fmaxf(fmaf(h1.y, sc1.y, sh1.y) + vz.y + wz.y, 0.f);
    bb.z = fmaxf(fmaf(h1.z, sc1.z, sh1.z) + vw.x + ww.x, 0.f);
    bb.w = fmaxf(fmaf(h1.w, sc1.w, sh1.w) + vw.y + ww.y, 0.f);
    float4 *po = (float4 *)(out + (size_t)row * 32 + m * 8);
    po[0] = a;
    po[1] = bb;
}

// ---------------------------------------------------------------------------
extern "C" void kernel_launch(void *const *d_in, const int *in_sizes, int n_in,
                              void *d_out, int out_size)
{
    const float *vf     = (const float *)d_in[0];
    const float *Wstem1 = (const float *)d_in[1];
    const float *Wstem2 = (const float *)d_in[2];
    const float *Wdown  = (const float *)d_in[3];
    const float *Wr1a   = (const float *)d_in[4];
    const float *Wr1b   = (const float *)d_in[5];
    const float *Wr2a   = (const float *)d_in[6];
    const float *Wr2b   = (const float *)d_in[7];
    const float *gam    = (const float *)d_in[8];
    const float *bet    = (const float *)d_in[9];
    const int *nbr0  = (const int *)d_in[10];
    const int *down1 = (const int *)d_in[11];
    const int *nbr1  = (const int *)d_in[12];

    int N0 = in_sizes[10] / 27;
    int N1 = in_sizes[11] / 8;

    float *bufA, *bufB, *bufC, *bufD, *stats;
    u32 *Bw, *Bs1;
    cudaGetSymbolAddress((void **)&bufA, g_bufA);
    cudaGetSymbolAddress((void **)&bufB, g_bufB);
    cudaGetSymbolAddress((void **)&bufC, g_bufC);
    cudaGetSymbolAddress((void **)&bufD, g_bufD);
    cudaGetSymbolAddress((void **)&stats, g_stats);
    cudaGetSymbolAddress((void **)&Bw, g_Bw);
    cudaGetSymbolAddress((void **)&Bs1, g_Bs1);

    u32 *uA = (u32 *)bufA, *uB = (u32 *)bufB, *uC = (u32 *)bufC, *uD = (u32 *)bufD;

    const size_t L27 = (size_t)27 * 512;
    u32 *B_stem2 = Bw + 0 * L27;
    u32 *B_r1a   = Bw + 1 * L27;
    u32 *B_r1b   = Bw + 2 * L27;
    u32 *B_r2a   = Bw + 3 * L27;
    u32 *B_r2b   = Bw + 4 * L27;
    u32 *B_down  = Bw + 5 * L27;

    size_t sm27 = (size_t)27 * 2048;   // 55296 B
    size_t sm8  = (size_t)8 * 2048;    // 16384 B
    cudaFuncSetAttribute(mma_conv_kernel<27>,
                         cudaFuncAttributeMaxDynamicSharedMemorySize, (int)sm27);
    cudaFuncSetAttribute(mma_conv_kernel<8>,
                         cudaFuncAttributeMaxDynamicSharedMemorySize, (int)sm8);

    int g0  = (N0 + 127) / 128;   // 128 rows per CTA
    int g1  = (N1 + 127) / 128;
    int a0n = (N0 * 4 + 255) / 256;
    int a1n = (N1 * 4 + 255) / 256;
    float invN0 = 1.f / (float)N0;
    float invN1 = 1.f / (float)N1;
    float *out = (float *)d_out;

    prep_all<<<294, 256>>>(Wstem2, Wr1a, Wr1b, Wr2a, Wr2b, Wdown, Wstem1, Bw, Bs1, stats);

    // stem1: vf -> raw A + stats0; apply -> split B
    stem1_kernel<<<g0, 256>>>(vf, nbr0, Bs1, bufA, stats + 0, N0);
    apply_split<<<a0n, 256>>>(bufA, stats + 0, gam + 0, bet + 0, invN0, uB, N0 * 4);

    // stem2: split B -> raw C + stats1; apply -> split A
    mma_conv_kernel<27><<<g0, 256, sm27>>>(uB, nbr0, (const uint4 *)B_stem2, bufC, stats + 64, N0);
    apply_split<<<a0n, 256>>>(bufC, stats + 64, gam + 32, bet + 32, invN0, uA, N0 * 4);

    // down: split A (level0) -> raw C + stats2; apply -> split D (= x1)
    mma_conv_kernel<8><<<g1, 256, sm8>>>(uA, down1, (const uint4 *)B_down, bufC, stats + 128, N1);
    apply_split<<<a1n, 256>>>(bufC, stats + 128, gam + 64, bet + 64, invN1, uD, N1 * 4);

    // r1a: split D -> raw A + stats3; apply -> split B
    mma_conv_kernel<27><<<g1, 256, sm27>>>(uD, nbr1, (const uint4 *)B_r1a, bufA, stats + 192, N1);
    apply_split<<<a1n, 256>>>(bufA, stats + 192, gam + 96, bet + 96, invN1, uB, N1 * 4);

    // r1b: split B -> raw A + stats4; res join with D -> split C (= x1')
    mma_conv_kernel<27><<<g1, 256, sm27>>>(uB, nbr1, (const uint4 *)B_r1b, bufA, stats + 256, N1);
    apply_res<<<a1n, 256>>>(bufA, stats + 256, gam + 128, bet + 128, uD, invN1, uC, N1 * 4);

    // r2a: split C -> raw A + stats5; apply -> split B
    mma_conv_kernel<27><<<g1, 256, sm27>>>(uC, nbr1, (const uint4 *)B_r2a, bufA, stats + 320, N1);
    apply_split<<<a1n, 256>>>(bufA, stats + 320, gam + 160, bet + 160, invN1, uB, N1 * 4);

    // r2b: split B -> raw A + stats6; final join with C -> fp32 out
    mma_conv_kernel<27><<<g1, 256, sm27>>>(uB, nbr1, (const uint4 *)B_r2b, bufA, stats + 384, N1);
    apply_final<<<a1n, 256>>>(bufA, stats + 384, gam + 192, bet + 192, uC, invN1, out, N1 * 4);
}